// round 1
// baseline (speedup 1.0000x reference)
#include <cuda_runtime.h>
#include <float.h>
#include <math.h>

// CapsuleConv2d: B=2, Cin=128, H=W=32, weight [O=16,L=16,M=16,3,3]
// G = 128/16 = 8 groups, N = G*9 = 72 input capsules per position,
// 256 output channels (o*16+l), k-means (dot) routing 3 iters, squash.
//
// Design: 1 CTA per (b,h,w) position, 256 threads, thread = ol.
//  - u[72] priors live in registers (thread-private column of the [72,256] matrix)
//  - routing reductions over l are 16-lane shfl_xor reductions
//  - softmax over n is computed online (single pass, 1 exp per n)
//  - weight pre-transposed to [p][m][ol] for coalesced loads (L1-resident)

__device__ float g_wT[9 * 16 * 256];  // [(p*16+m)*256 + ol]

__global__ void wt_transpose(const float* __restrict__ w) {
    int idx = blockIdx.x * 256 + threadIdx.x;   // 36864 total
    int p  = idx >> 12;          // 0..8
    int m  = (idx >> 8) & 15;    // 0..15
    int ol = idx & 255;          // 0..255
    // weight flat: (((o*16+l)*16+m)*3+i)*3+j = (ol*16+m)*9 + p
    g_wT[idx] = w[(ol * 16 + m) * 9 + p];
}

__global__ __launch_bounds__(256, 2)
void capsule_kernel(const float* __restrict__ x, float* __restrict__ out) {
    __shared__ float xs[9 * 128];   // xs[p*128 + c], patch pixels

    const int tid = threadIdx.x;    // ol = o*16 + l
    const int bid = blockIdx.x;     // b*1024 + h*32 + w
    const int b = bid >> 10;
    const int h = (bid >> 5) & 31;
    const int w = bid & 31;

    // Stage the 3x3 patch (zero-padded) into smem: 9 pixels x 128 channels
    for (int idx = tid; idx < 9 * 128; idx += 256) {
        int p = idx >> 7;
        int c = idx & 127;
        int hh = h + p / 3 - 1;
        int ww = w + p % 3 - 1;
        float v = 0.f;
        if ((unsigned)hh < 32u && (unsigned)ww < 32u)
            v = x[((b * 128 + c) * 32 + hh) * 32 + ww];
        xs[idx] = v;
    }
    __syncthreads();

    // ---- priors: u[n=g*9+p] = sum_m xs[p][g*16+m] * W[ol][m][p] ----
    float u[72];
    float vmean = 0.f;
    const float4* xs4 = reinterpret_cast<const float4*>(xs);
#pragma unroll
    for (int p = 0; p < 9; p++) {
        float wr[16];
#pragma unroll
        for (int m = 0; m < 16; m++)
            wr[m] = g_wT[(p * 16 + m) * 256 + tid];   // coalesced, L1-hot
#pragma unroll
        for (int g = 0; g < 8; g++) {
            float4 a0 = xs4[p * 32 + g * 4 + 0];
            float4 a1 = xs4[p * 32 + g * 4 + 1];
            float4 a2 = xs4[p * 32 + g * 4 + 2];
            float4 a3 = xs4[p * 32 + g * 4 + 3];
            float acc;
            acc = a0.x * wr[0];
            acc = fmaf(a0.y, wr[1], acc);
            acc = fmaf(a0.z, wr[2], acc);
            acc = fmaf(a0.w, wr[3], acc);
            acc = fmaf(a1.x, wr[4], acc);
            acc = fmaf(a1.y, wr[5], acc);
            acc = fmaf(a1.z, wr[6], acc);
            acc = fmaf(a1.w, wr[7], acc);
            acc = fmaf(a2.x, wr[8], acc);
            acc = fmaf(a2.y, wr[9], acc);
            acc = fmaf(a2.z, wr[10], acc);
            acc = fmaf(a2.w, wr[11], acc);
            acc = fmaf(a3.x, wr[12], acc);
            acc = fmaf(a3.y, wr[13], acc);
            acc = fmaf(a3.z, wr[14], acc);
            acc = fmaf(a3.w, wr[15], acc);
            u[g * 9 + p] = acc;
            vmean += acc;
        }
    }

    // ---- k-means routing (dot similarity), 3 iterations ----
    float v = vmean * (1.f / 72.f);   // initial v = mean over n

#pragma unroll 1
    for (int it = 0; it < 3; it++) {
        // ||v|| over l (16-lane group reduction)
        float sq = v * v;
        sq += __shfl_xor_sync(0xffffffffu, sq, 8);
        sq += __shfl_xor_sync(0xffffffffu, sq, 4);
        sq += __shfl_xor_sync(0xffffffffu, sq, 2);
        sq += __shfl_xor_sync(0xffffffffu, sq, 1);
        float vn = v / fmaxf(sqrtf(sq), 1e-12f);

        // online softmax over n, fused with weighted accumulation of u
        float mmax = -FLT_MAX, ssum = 0.f, vacc = 0.f;
#pragma unroll
        for (int n = 0; n < 72; n++) {
            float part = u[n] * vn;
            part += __shfl_xor_sync(0xffffffffu, part, 8);
            part += __shfl_xor_sync(0xffffffffu, part, 4);
            part += __shfl_xor_sync(0xffffffffu, part, 2);
            part += __shfl_xor_sync(0xffffffffu, part, 1);
            // part == logit[n][o], identical on all 16 lanes of the group
            if (part > mmax) {
                float sc = __expf(mmax - part);   // 0 on first n (underflow)
                ssum = fmaf(ssum, sc, 1.f);
                vacc = fmaf(vacc, sc, u[n]);
                mmax = part;
            } else {
                float e = __expf(part - mmax);
                ssum += e;
                vacc = fmaf(e, u[n], vacc);
            }
        }
        v = vacc / ssum;
    }

    // ---- squash: v * ||v|| / (1 + ||v||^2) ----
    float sq = v * v;
    sq += __shfl_xor_sync(0xffffffffu, sq, 8);
    sq += __shfl_xor_sync(0xffffffffu, sq, 4);
    sq += __shfl_xor_sync(0xffffffffu, sq, 2);
    sq += __shfl_xor_sync(0xffffffffu, sq, 1);
    float norm = sqrtf(sq);
    float ov = v * (norm / (1.f + sq));

    // out[b][ol][h][w]
    out[((b * 256 + tid) * 32 + h) * 32 + w] = ov;
}

extern "C" void kernel_launch(void* const* d_in, const int* in_sizes, int n_in,
                              void* d_out, int out_size) {
    const float* x = (const float*)d_in[0];    // [2,128,32,32]
    const float* w = (const float*)d_in[1];    // [16,16,16,3,3]
    float* out = (float*)d_out;                // [2,256,32,32]

    wt_transpose<<<144, 256>>>(w);
    capsule_kernel<<<2048, 256>>>(x, out);
}

// round 3
// speedup vs baseline: 1.5330x; 1.5330x over previous
#include <cuda_runtime.h>
#include <float.h>
#include <math.h>

// CapsuleConv2d: B=2, Cin=128, H=W=32, weight [O=16,L=16,M=16,3,3]
// 1 CTA per (b,h,w), 256 threads, thread = ol = o*16+l.
// Priors in registers (u[72]); routing with distributed logits:
//   - butterfly transpose-reduce: 16 logits per 15 shfls
//   - batch softmax: 5 exp per thread per iteration
//   - v-update via per-source broadcasts
// Priors use packed fp32x2 FMA (sm_103a) with pre-paired weights.

__device__ float2 g_wT2[9 * 8 * 256];  // [(p*8+mp)*256 + ol] = (W[ol][2mp][p], W[ol][2mp+1][p])

__global__ void wt_transpose(const float* __restrict__ w) {
    int idx = blockIdx.x * 256 + threadIdx.x;   // 18432 total
    int p  = idx >> 11;          // 0..8
    int mp = (idx >> 8) & 7;     // 0..7 (m pair)
    int ol = idx & 255;
    // weight flat: (ol*16+m)*9 + p
    g_wT2[idx] = make_float2(w[(ol * 16 + 2 * mp) * 9 + p],
                             w[(ol * 16 + 2 * mp + 1) * 9 + p]);
}

__device__ __forceinline__ unsigned long long fma2(unsigned long long a,
                                                   unsigned long long b,
                                                   unsigned long long c) {
    unsigned long long d;
    asm("fma.rn.f32x2 %0, %1, %2, %3;" : "=l"(d) : "l"(a), "l"(b), "l"(c));
    return d;
}

__global__ __launch_bounds__(256, 2)
void capsule_kernel(const float* __restrict__ x, float* __restrict__ out) {
    __shared__ __align__(16) float xs[9 * 128];   // xs[p*128 + c]

    const int tid = threadIdx.x;    // ol
    const int bid = blockIdx.x;     // b*1024 + h*32 + w
    const int b = bid >> 10;
    const int h = (bid >> 5) & 31;
    const int w = bid & 31;

    // Stage 3x3 patch (zero-padded): 9 pixels x 128 channels
    for (int idx = tid; idx < 9 * 128; idx += 256) {
        int p = idx >> 7;
        int c = idx & 127;
        int hh = h + p / 3 - 1;
        int ww = w + p % 3 - 1;
        float v = 0.f;
        if ((unsigned)hh < 32u && (unsigned)ww < 32u)
            v = x[((b * 128 + c) * 32 + hh) * 32 + ww];
        xs[idx] = v;
    }
    __syncthreads();

    // ---- priors: u[g*9+p] = sum_m xs[p][g*16+m] * W[ol][m][p], via f32x2 ----
    float u[72];
    float vmean = 0.f;
    const ulonglong2* xs2 = reinterpret_cast<const ulonglong2*>(xs);   // 9*32 elems
    const unsigned long long* wp = reinterpret_cast<const unsigned long long*>(g_wT2);
#pragma unroll
    for (int p = 0; p < 9; p++) {
        unsigned long long w2[8];
#pragma unroll
        for (int mp = 0; mp < 8; mp++)
            w2[mp] = wp[(p * 8 + mp) * 256 + tid];   // coalesced, L1-hot
#pragma unroll
        for (int g = 0; g < 8; g++) {
            ulonglong2 A = xs2[p * 32 + g * 4 + 0];
            ulonglong2 Bq = xs2[p * 32 + g * 4 + 1];
            ulonglong2 C = xs2[p * 32 + g * 4 + 2];
            ulonglong2 D = xs2[p * 32 + g * 4 + 3];
            unsigned long long acc = fma2(A.x, w2[0], 0ull);
            acc = fma2(A.y,  w2[1], acc);
            acc = fma2(Bq.x, w2[2], acc);
            acc = fma2(Bq.y, w2[3], acc);
            acc = fma2(C.x,  w2[4], acc);
            acc = fma2(C.y,  w2[5], acc);
            acc = fma2(D.x,  w2[6], acc);
            acc = fma2(D.y,  w2[7], acc);
            float lo, hi;
            asm("mov.b64 {%0, %1}, %2;" : "=f"(lo), "=f"(hi) : "l"(acc));
            float s = lo + hi;
            u[g * 9 + p] = s;
            vmean += s;
        }
    }

    // ---- k-means routing (dot), 3 iterations, distributed logits ----
    const unsigned FULL = 0xffffffffu;
    const int lane = tid & 15;   // l
    float v = vmean * (1.f / 72.f);

#pragma unroll 1
    for (int it = 0; it < 3; it++) {
        // ||v|| over the 16-lane group
        float sq = v * v;
        sq += __shfl_xor_sync(FULL, sq, 8);
        sq += __shfl_xor_sync(FULL, sq, 4);
        sq += __shfl_xor_sync(FULL, sq, 2);
        sq += __shfl_xor_sync(FULL, sq, 1);
        float vn = v / fmaxf(sqrtf(sq), 1e-12f);

        // logits, distributed: after butterfly, lane holds logit[n=16j+lane]
        float lg[5];
#pragma unroll
        for (int j = 0; j < 5; j++) {
            float t[16];
#pragma unroll
            for (int k = 0; k < 16; k++) {
                int n = j * 16 + k;
                t[k] = (n < 72) ? u[n] * vn : 0.f;
            }
#pragma unroll
            for (int m = 8; m >= 1; m >>= 1) {
                bool up = (lane & m) != 0;
#pragma unroll
                for (int k = 0; k < m; k++) {
                    float a = t[k], c2 = t[k + m];
                    float keep = up ? c2 : a;
                    float send = up ? a : c2;
                    t[k] = keep + __shfl_xor_sync(FULL, send, m);
                }
            }
            lg[j] = t[0];
        }
        if (lane >= 8) lg[4] = -FLT_MAX;   // n = 64+lane >= 72 invalid

        // batch softmax over 72 distributed logits
        float mx = fmaxf(fmaxf(fmaxf(lg[0], lg[1]), fmaxf(lg[2], lg[3])), lg[4]);
        mx = fmaxf(mx, __shfl_xor_sync(FULL, mx, 8));
        mx = fmaxf(mx, __shfl_xor_sync(FULL, mx, 4));
        mx = fmaxf(mx, __shfl_xor_sync(FULL, mx, 2));
        mx = fmaxf(mx, __shfl_xor_sync(FULL, mx, 1));

        float e0 = __expf(lg[0] - mx);
        float e1 = __expf(lg[1] - mx);
        float e2 = __expf(lg[2] - mx);
        float e3 = __expf(lg[3] - mx);
        float e4 = __expf(lg[4] - mx);   // 0 for invalid lanes
        float ssum = ((e0 + e1) + (e2 + e3)) + e4;
        ssum += __shfl_xor_sync(FULL, ssum, 8);
        ssum += __shfl_xor_sync(FULL, ssum, 4);
        ssum += __shfl_xor_sync(FULL, ssum, 2);
        ssum += __shfl_xor_sync(FULL, ssum, 1);

        // v = sum_n e[n]*u[n] / ssum ; e[16j+s] lives on lane s
        float va0 = 0.f, va1 = 0.f, va2 = 0.f, va3 = 0.f;
#pragma unroll
        for (int s = 0; s < 16; s++) {
            float p0 = __shfl_sync(FULL, e0, s, 16);
            float p1 = __shfl_sync(FULL, e1, s, 16);
            float p2 = __shfl_sync(FULL, e2, s, 16);
            float p3 = __shfl_sync(FULL, e3, s, 16);
            va0 = fmaf(p0, u[s], va0);
            va1 = fmaf(p1, u[16 + s], va1);
            va2 = fmaf(p2, u[32 + s], va2);
            va3 = fmaf(p3, u[48 + s], va3);
        }
#pragma unroll
        for (int s = 0; s < 8; s++) {
            float p4 = __shfl_sync(FULL, e4, s, 16);
            va0 = fmaf(p4, u[64 + s], va0);
        }
        v = (((va0 + va1) + (va2 + va3))) / ssum;
    }

    // ---- squash ----
    float sq = v * v;
    sq += __shfl_xor_sync(FULL, sq, 8);
    sq += __shfl_xor_sync(FULL, sq, 4);
    sq += __shfl_xor_sync(FULL, sq, 2);
    sq += __shfl_xor_sync(FULL, sq, 1);
    float norm = sqrtf(sq);
    float ov = v * (norm / (1.f + sq));

    out[((b * 256 + tid) * 32 + h) * 32 + w] = ov;
}

extern "C" void kernel_launch(void* const* d_in, const int* in_sizes, int n_in,
                              void* d_out, int out_size) {
    const float* x = (const float*)d_in[0];    // [2,128,32,32]
    const float* w = (const float*)d_in[1];    // [16,16,16,3,3]
    float* out = (float*)d_out;                // [2,256,32,32]

    wt_transpose<<<72, 256>>>(w);
    capsule_kernel<<<2048, 256>>>(x, out);
}

// round 4
// speedup vs baseline: 2.4810x; 1.6184x over previous
#include <cuda_runtime.h>
#include <float.h>
#include <math.h>

// CapsuleConv2d: B=2, Cin=128, H=W=32, weight [O=16,L=16,M=16,3,3]
// 1 CTA per (b,h,w), 256 threads, thread = ol = o*16+l.
// Priors in registers; routing in TRANSPOSED register layout:
//   - one-time 16x16 in-register butterfly transpose (rows on lanes)
//   - v kept replicated across the 16-lane group -> logits/norm are local FMA
//   - per-iter cross-lane work: 4 (sum) + 15 (reduce-scatter) + 16 (all-gather) shfl

__device__ float4 g_wT4[9 * 4 * 256];  // [(p*4+q)*256 + ol] = W[ol][4q..4q+3][p]

__global__ void wt_transpose(const float* __restrict__ w) {
    int idx = blockIdx.x * 256 + threadIdx.x;   // 9216 total
    int p  = idx >> 10;          // 0..8
    int q  = (idx >> 8) & 3;     // m quad
    int ol = idx & 255;
    // weight flat: (ol*16+m)*9 + p
    g_wT4[idx] = make_float4(w[(ol * 16 + 4 * q + 0) * 9 + p],
                             w[(ol * 16 + 4 * q + 1) * 9 + p],
                             w[(ol * 16 + 4 * q + 2) * 9 + p],
                             w[(ol * 16 + 4 * q + 3) * 9 + p]);
}

__device__ __forceinline__ unsigned long long fma2(unsigned long long a,
                                                   unsigned long long b,
                                                   unsigned long long c) {
    unsigned long long d;
    asm("fma.rn.f32x2 %0, %1, %2, %3;" : "=l"(d) : "l"(a), "l"(b), "l"(c));
    return d;
}

__global__ __launch_bounds__(256, 2)
void capsule_kernel(const float* __restrict__ x, float* __restrict__ out) {
    __shared__ __align__(16) float xs[9 * 128];   // xs[p*128 + c]

    const unsigned FULL = 0xffffffffu;
    const int tid = threadIdx.x;    // ol
    const int lane = tid & 15;      // l (lane within 16-group)
    const int bid = blockIdx.x;     // b*1024 + h*32 + w
    const int b = bid >> 10;
    const int h = (bid >> 5) & 31;
    const int w = bid & 31;

    // Stage 3x3 patch (zero-padded): 9 pixels x 128 channels
    for (int idx = tid; idx < 9 * 128; idx += 256) {
        int p = idx >> 7;
        int c = idx & 127;
        int hh = h + p / 3 - 1;
        int ww = w + p % 3 - 1;
        float v = 0.f;
        if ((unsigned)hh < 32u && (unsigned)ww < 32u)
            v = x[((b * 128 + c) * 32 + hh) * 32 + ww];
        xs[idx] = v;
    }
    __syncthreads();

    // ---- priors: u[g*9+p] = sum_m xs[p][g*16+m] * W[ol][m][p] (f32x2) ----
    float u[80];                     // 72 priors + 8 zero pad
    float vmean = 0.f;
    const ulonglong2* xs2 = reinterpret_cast<const ulonglong2*>(xs);
    const ulonglong2* wp = reinterpret_cast<const ulonglong2*>(g_wT4);
#pragma unroll
    for (int p = 0; p < 9; p++) {
        ulonglong2 w0 = wp[(p * 4 + 0) * 256 + tid];   // m 0..3
        ulonglong2 w1 = wp[(p * 4 + 1) * 256 + tid];   // m 4..7
        ulonglong2 w2 = wp[(p * 4 + 2) * 256 + tid];   // m 8..11
        ulonglong2 w3 = wp[(p * 4 + 3) * 256 + tid];   // m 12..15
#pragma unroll
        for (int g = 0; g < 8; g++) {
            ulonglong2 A = xs2[p * 32 + g * 4 + 0];
            ulonglong2 Bq = xs2[p * 32 + g * 4 + 1];
            ulonglong2 C = xs2[p * 32 + g * 4 + 2];
            ulonglong2 D = xs2[p * 32 + g * 4 + 3];
            unsigned long long acc = fma2(A.x, w0.x, 0ull);
            acc = fma2(A.y,  w0.y, acc);
            acc = fma2(Bq.x, w1.x, acc);
            acc = fma2(Bq.y, w1.y, acc);
            acc = fma2(C.x,  w2.x, acc);
            acc = fma2(C.y,  w2.y, acc);
            acc = fma2(D.x,  w3.x, acc);
            acc = fma2(D.y,  w3.y, acc);
            float lo, hi;
            asm("mov.b64 {%0, %1}, %2;" : "=f"(lo), "=f"(hi) : "l"(acc));
            float s = lo + hi;
            u[g * 9 + p] = s;
            vmean += s;
        }
    }
#pragma unroll
    for (int k = 72; k < 80; k++) u[k] = 0.f;

    // ---- one-time transpose: u[j*16+k] becomes U[16j+lane][k] ----
#pragma unroll
    for (int j = 0; j < 5; j++) {
        float t[16];
#pragma unroll
        for (int k = 0; k < 16; k++) t[k] = u[j * 16 + k];
#pragma unroll
        for (int mm = 0; mm < 4; mm++) {
            const int m = 8 >> mm;
            bool up = (lane & m) != 0;
#pragma unroll
            for (int k = 0; k < 16; k++) {
                if (k & m) continue;
                float send = up ? t[k] : t[k | m];
                float got = __shfl_xor_sync(FULL, send, m);
                if (up) t[k] = got; else t[k | m] = got;
            }
        }
#pragma unroll
        for (int k = 0; k < 16; k++) u[j * 16 + k] = t[k];
    }

    // ---- initial v, replicated across the 16-lane group ----
    float v_own = vmean * (1.f / 72.f);
    float vv[16];
#pragma unroll
    for (int k = 0; k < 16; k++) vv[k] = __shfl_sync(FULL, v_own, k, 16);

    // ---- k-means routing, 3 iterations ----
    float ov = 0.f;
#pragma unroll
    for (int it = 0; it < 3; it++) {
        // ||v||: local (vv replicated)
        float sq = 0.f;
#pragma unroll
        for (int k = 0; k < 16; k++) sq = fmaf(vv[k], vv[k], sq);
        float rn = 1.0f / fmaxf(sqrtf(sq), 1e-12f);

        // logits: local dot products; e = exp(logit) (softmax shift skipped:
        // logits bounded small, mathematically identical)
        float e[5];
#pragma unroll
        for (int j = 0; j < 5; j++) {
            float d = 0.f;
#pragma unroll
            for (int k = 0; k < 16; k++) d = fmaf(u[j * 16 + k], vv[k], d);
            e[j] = __expf(d * rn);
        }
        if (lane >= 8) e[4] = 0.f;    // n = 64+lane >= 72 invalid

        float ssum = ((e[0] + e[1]) + (e[2] + e[3])) + e[4];
        ssum += __shfl_xor_sync(FULL, ssum, 8);
        ssum += __shfl_xor_sync(FULL, ssum, 4);
        ssum += __shfl_xor_sync(FULL, ssum, 2);
        ssum += __shfl_xor_sync(FULL, ssum, 1);

        // weighted accumulation: local
        float a[16];
#pragma unroll
        for (int k = 0; k < 16; k++) {
            float acc = e[0] * u[k];
            acc = fmaf(e[1], u[16 + k], acc);
            acc = fmaf(e[2], u[32 + k], acc);
            acc = fmaf(e[3], u[48 + k], acc);
            acc = fmaf(e[4], u[64 + k], acc);
            a[k] = acc;
        }

        // reduce-scatter over the 16-lane group: lane s ends with total a[s]
#pragma unroll
        for (int mm = 0; mm < 4; mm++) {
            const int m = 8 >> mm;
            bool up = (lane & m) != 0;
#pragma unroll
            for (int i = 0; i < 16; i++) {
                if (i >= m) continue;
                float send = up ? a[i] : a[i + m];
                float got = __shfl_xor_sync(FULL, send, m);
                a[i] = (up ? a[i + m] : a[i]) + got;
            }
        }
        float vfin = a[0] / ssum;    // v[l = lane]

        if (it < 2) {
            // re-replicate for next iteration
#pragma unroll
            for (int k = 0; k < 16; k++) vv[k] = __shfl_sync(FULL, vfin, k, 16);
        } else {
            // squash on the distributed final v
            float s2 = vfin * vfin;
            s2 += __shfl_xor_sync(FULL, s2, 8);
            s2 += __shfl_xor_sync(FULL, s2, 4);
            s2 += __shfl_xor_sync(FULL, s2, 2);
            s2 += __shfl_xor_sync(FULL, s2, 1);
            float norm = sqrtf(s2);
            ov = vfin * (norm / (1.f + s2));
        }
    }

    // out[b][ol][h][w]
    out[((b * 256 + tid) * 32 + h) * 32 + w] = ov;
}

extern "C" void kernel_launch(void* const* d_in, const int* in_sizes, int n_in,
                              void* d_out, int out_size) {
    const float* x = (const float*)d_in[0];    // [2,128,32,32]
    const float* w = (const float*)d_in[1];    // [16,16,16,3,3]
    float* out = (float*)d_out;                // [2,256,32,32]

    wt_transpose<<<36, 256>>>(w);
    capsule_kernel<<<2048, 256>>>(x, out);
}

// round 6
// speedup vs baseline: 2.7752x; 1.1186x over previous
#include <cuda_runtime.h>
#include <float.h>
#include <math.h>

// CapsuleConv2d: B=2, Cin=128, H=W=32, weight [O=16,L=16,M=16,3,3]
// 1 CTA per (b,h,w), 256 threads, thread = ol = o*16+l.
//  - priors computed per-thread (f32x2 FMA), streamed to smem u[n][ol] (STS coalesced)
//  - transpose realized by reading rows back: thread gets u[16j+lane][16 l's of its group]
//  - routing fully local: v replicated in regs; per-iter cross-lane = 4+15+16 shfl

__device__ float4 g_wT4[9 * 4 * 256];  // [(p*4+q)*256 + ol] = W[ol][4q..4q+3][p]

__global__ void wt_transpose(const float* __restrict__ w) {
    int idx = blockIdx.x * 256 + threadIdx.x;   // 9216 total
    int p  = idx >> 10;
    int q  = (idx >> 8) & 3;
    int ol = idx & 255;
    g_wT4[idx] = make_float4(w[(ol * 16 + 4 * q + 0) * 9 + p],
                             w[(ol * 16 + 4 * q + 1) * 9 + p],
                             w[(ol * 16 + 4 * q + 2) * 9 + p],
                             w[(ol * 16 + 4 * q + 3) * 9 + p]);
}

__device__ __forceinline__ unsigned long long fma2(unsigned long long a,
                                                   unsigned long long b,
                                                   unsigned long long c) {
    unsigned long long d;
    asm("fma.rn.f32x2 %0, %1, %2, %3;" : "=l"(d) : "l"(a), "l"(b), "l"(c));
    return d;
}

#define USTRIDE 260   // padded row stride (floats): 65*16B -> conflict-free float4 reads

__global__ __launch_bounds__(256, 2)
void capsule_kernel(const float* __restrict__ x, float* __restrict__ out) {
    extern __shared__ __align__(16) float smem[];
    float* xs = smem;            // 9*128 patch
    float* su = smem + 1152;     // 80 * USTRIDE transpose buffer

    const unsigned FULL = 0xffffffffu;
    const int tid = threadIdx.x;     // ol
    const int lane = tid & 15;       // l
    const int grp = tid >> 4;        // o
    const int bid = blockIdx.x;
    const int b = bid >> 10;
    const int h = (bid >> 5) & 31;
    const int w = bid & 31;

    // Stage 3x3 patch (zero-padded): 9 pixels x 128 channels
    for (int idx = tid; idx < 9 * 128; idx += 256) {
        int p = idx >> 7;
        int c = idx & 127;
        int hh = h + p / 3 - 1;
        int ww = w + p % 3 - 1;
        float v = 0.f;
        if ((unsigned)hh < 32u && (unsigned)ww < 32u)
            v = x[((b * 128 + c) * 32 + hh) * 32 + ww];
        xs[idx] = v;
    }
    __syncthreads();

    // ---- priors: u[g*9+p][tid] streamed to smem; vmean accumulated ----
    float vmean = 0.f;
    const ulonglong2* xs2 = reinterpret_cast<const ulonglong2*>(xs);
    const ulonglong2* wp = reinterpret_cast<const ulonglong2*>(g_wT4);
#pragma unroll
    for (int p = 0; p < 9; p++) {
        ulonglong2 w0 = wp[(p * 4 + 0) * 256 + tid];
        ulonglong2 w1 = wp[(p * 4 + 1) * 256 + tid];
        ulonglong2 w2 = wp[(p * 4 + 2) * 256 + tid];
        ulonglong2 w3 = wp[(p * 4 + 3) * 256 + tid];
#pragma unroll
        for (int g = 0; g < 8; g++) {
            ulonglong2 A  = xs2[p * 32 + g * 4 + 0];
            ulonglong2 Bq = xs2[p * 32 + g * 4 + 1];
            ulonglong2 C  = xs2[p * 32 + g * 4 + 2];
            ulonglong2 D  = xs2[p * 32 + g * 4 + 3];
            unsigned long long acc = fma2(A.x, w0.x, 0ull);
            acc = fma2(A.y,  w0.y, acc);
            acc = fma2(Bq.x, w1.x, acc);
            acc = fma2(Bq.y, w1.y, acc);
            acc = fma2(C.x,  w2.x, acc);
            acc = fma2(C.y,  w2.y, acc);
            acc = fma2(D.x,  w3.x, acc);
            acc = fma2(D.y,  w3.y, acc);
            float lo, hi;
            asm("mov.b64 {%0, %1}, %2;" : "=f"(lo), "=f"(hi) : "l"(acc));
            float s = lo + hi;
            su[(g * 9 + p) * USTRIDE + tid] = s;
            vmean += s;
        }
    }
    __syncthreads();

    // ---- read transposed rows: rows[j][k] = u[16j+lane][grp*16+k] ----
    float rows[80];
#pragma unroll
    for (int j = 0; j < 5; j++) {
        int n = 16 * j + lane;
        if (n >= 72) n -= 72;          // wrap: finite data, masked later (e4=0)
        const float4* rp = reinterpret_cast<const float4*>(su + n * USTRIDE + grp * 16);
        float4 r0 = rp[0], r1 = rp[1], r2 = rp[2], r3 = rp[3];
        rows[j * 16 + 0] = r0.x;  rows[j * 16 + 1] = r0.y;
        rows[j * 16 + 2] = r0.z;  rows[j * 16 + 3] = r0.w;
        rows[j * 16 + 4] = r1.x;  rows[j * 16 + 5] = r1.y;
        rows[j * 16 + 6] = r1.z;  rows[j * 16 + 7] = r1.w;
        rows[j * 16 + 8] = r2.x;  rows[j * 16 + 9] = r2.y;
        rows[j * 16 + 10] = r2.z; rows[j * 16 + 11] = r2.w;
        rows[j * 16 + 12] = r3.x; rows[j * 16 + 13] = r3.y;
        rows[j * 16 + 14] = r3.z; rows[j * 16 + 15] = r3.w;
    }

    // ---- initial v, replicated across the 16-lane group ----
    float v_own = vmean * (1.f / 72.f);
    float vv[16];
#pragma unroll
    for (int k = 0; k < 16; k++) vv[k] = __shfl_sync(FULL, v_own, k, 16);

    // ---- k-means routing, 3 iterations ----
    float ov = 0.f;
#pragma unroll
    for (int it = 0; it < 3; it++) {
        // ||v||: local (vv replicated)
        float sq = 0.f;
#pragma unroll
        for (int k = 0; k < 16; k++) sq = fmaf(vv[k], vv[k], sq);
        float rn = rsqrtf(fmaxf(sq, 1e-24f));

        // logits -> exp (softmax shift skipped: logits bounded small)
        float e[5];
#pragma unroll
        for (int j = 0; j < 5; j++) {
            float d = 0.f;
#pragma unroll
            for (int k = 0; k < 16; k++) d = fmaf(rows[j * 16 + k], vv[k], d);
            e[j] = __expf(d * rn);
        }
        if (lane >= 8) e[4] = 0.f;    // n = 64+lane >= 72 invalid

        float ssum = ((e[0] + e[1]) + (e[2] + e[3])) + e[4];
        ssum += __shfl_xor_sync(FULL, ssum, 8);
        ssum += __shfl_xor_sync(FULL, ssum, 4);
        ssum += __shfl_xor_sync(FULL, ssum, 2);
        ssum += __shfl_xor_sync(FULL, ssum, 1);

        // weighted accumulation: local
        float a[16];
#pragma unroll
        for (int k = 0; k < 16; k++) {
            float acc = e[0] * rows[k];
            acc = fmaf(e[1], rows[16 + k], acc);
            acc = fmaf(e[2], rows[32 + k], acc);
            acc = fmaf(e[3], rows[48 + k], acc);
            acc = fmaf(e[4], rows[64 + k], acc);
            a[k] = acc;
        }

        // reduce-scatter over 16-lane group: lane s ends with total a[s]
#pragma unroll
        for (int mm = 0; mm < 4; mm++) {
            const int m = 8 >> mm;
            bool up = (lane & m) != 0;
#pragma unroll
            for (int i = 0; i < 16; i++) {
                if (i >= m) continue;
                float send = up ? a[i] : a[i + m];
                float got = __shfl_xor_sync(FULL, send, m);
                a[i] = (up ? a[i + m] : a[i]) + got;
            }
        }
        float vfin = __fdividef(a[0], ssum);   // v[l = lane]

        if (it < 2) {
#pragma unroll
            for (int k = 0; k < 16; k++) vv[k] = __shfl_sync(FULL, vfin, k, 16);
        } else {
            float s2 = vfin * vfin;
            s2 += __shfl_xor_sync(FULL, s2, 8);
            s2 += __shfl_xor_sync(FULL, s2, 4);
            s2 += __shfl_xor_sync(FULL, s2, 2);
            s2 += __shfl_xor_sync(FULL, s2, 1);
            float norm = sqrtf(s2);
            ov = vfin * __fdividef(norm, 1.f + s2);
        }
    }

    out[((b * 256 + tid) * 32 + h) * 32 + w] = ov;
}

extern "C" void kernel_launch(void* const* d_in, const int* in_sizes, int n_in,
                              void* d_out, int out_size) {
    const float* x = (const float*)d_in[0];    // [2,128,32,32]
    const float* w = (const float*)d_in[1];    // [16,16,16,3,3]
    float* out = (float*)d_out;                // [2,256,32,32]

    const int smem_bytes = (1152 + 80 * USTRIDE) * 4;   // 87808 B
    cudaFuncSetAttribute(capsule_kernel,
                         cudaFuncAttributeMaxDynamicSharedMemorySize, smem_bytes);

    wt_transpose<<<36, 256>>>(w);
    capsule_kernel<<<2048, 256, smem_bytes>>>(x, out);
}

// round 7
// speedup vs baseline: 3.0151x; 1.0864x over previous
#include <cuda_runtime.h>
#include <float.h>
#include <math.h>

// CapsuleConv2d: B=2, Cin=128, H=W=32, weight [O=16,L=16,M=16,3,3]
// 1 CTA per (b,h,w), 128 threads, thread computes TWO columns: ol = tid, tid+128.
//  - xs LDS amortized over 2 columns (halves LSU pressure in priors)
//  - priors streamed to smem u[n][ol]; routing reads transposed rows back
//  - routing: 2 sequential passes per thread (register-friendly), v replicated,
//    per-iter cross-lane = 4 + 15 + 16 shfl within 16-lane groups

__device__ float4 g_wT4[9 * 4 * 256];  // [(p*4+q)*256 + ol] = W[ol][4q..4q+3][p]

__global__ void wt_transpose(const float* __restrict__ w) {
    int idx = blockIdx.x * 256 + threadIdx.x;   // 9216 total
    int p  = idx >> 10;
    int q  = (idx >> 8) & 3;
    int ol = idx & 255;
    g_wT4[idx] = make_float4(w[(ol * 16 + 4 * q + 0) * 9 + p],
                             w[(ol * 16 + 4 * q + 1) * 9 + p],
                             w[(ol * 16 + 4 * q + 2) * 9 + p],
                             w[(ol * 16 + 4 * q + 3) * 9 + p]);
}

__device__ __forceinline__ unsigned long long fma2(unsigned long long a,
                                                   unsigned long long b,
                                                   unsigned long long c) {
    unsigned long long d;
    asm("fma.rn.f32x2 %0, %1, %2, %3;" : "=l"(d) : "l"(a), "l"(b), "l"(c));
    return d;
}

#define USTRIDE 260   // padded row stride (floats): conflict-free float4 reads

__global__ __launch_bounds__(128, 2)
void capsule_kernel(const float* __restrict__ x, float* __restrict__ out) {
    extern __shared__ __align__(16) float smem[];
    float* xs = smem;            // 9*128 patch
    float* su = smem + 1152;     // 72 * USTRIDE transpose buffer

    const unsigned FULL = 0xffffffffu;
    const int tid = threadIdx.x;     // colA = tid, colB = tid + 128
    const int lane = tid & 15;       // l
    const int grp = tid >> 4;        // o for colA (0..7); colB is grp+8
    const int bid = blockIdx.x;
    const int b = bid >> 10;
    const int h = (bid >> 5) & 31;
    const int w = bid & 31;

    // Stage 3x3 patch (zero-padded): 9 pixels x 128 channels
    for (int idx = tid; idx < 9 * 128; idx += 128) {
        int p = idx >> 7;
        int c = idx & 127;
        int hh = h + p / 3 - 1;
        int ww = w + p % 3 - 1;
        float v = 0.f;
        if ((unsigned)hh < 32u && (unsigned)ww < 32u)
            v = x[((b * 128 + c) * 32 + hh) * 32 + ww];
        xs[idx] = v;
    }
    __syncthreads();

    // ---- priors for BOTH columns; each xs load feeds 2 FMA chains ----
    float vmeanA = 0.f, vmeanB = 0.f;
    const ulonglong2* xs2 = reinterpret_cast<const ulonglong2*>(xs);
    const ulonglong2* wp = reinterpret_cast<const ulonglong2*>(g_wT4);
#pragma unroll
    for (int p = 0; p < 9; p++) {
        ulonglong2 wa0 = wp[(p * 4 + 0) * 256 + tid];
        ulonglong2 wa1 = wp[(p * 4 + 1) * 256 + tid];
        ulonglong2 wa2 = wp[(p * 4 + 2) * 256 + tid];
        ulonglong2 wa3 = wp[(p * 4 + 3) * 256 + tid];
        ulonglong2 wb0 = wp[(p * 4 + 0) * 256 + tid + 128];
        ulonglong2 wb1 = wp[(p * 4 + 1) * 256 + tid + 128];
        ulonglong2 wb2 = wp[(p * 4 + 2) * 256 + tid + 128];
        ulonglong2 wb3 = wp[(p * 4 + 3) * 256 + tid + 128];
#pragma unroll
        for (int g = 0; g < 8; g++) {
            ulonglong2 A  = xs2[p * 32 + g * 4 + 0];
            ulonglong2 Bq = xs2[p * 32 + g * 4 + 1];
            ulonglong2 C  = xs2[p * 32 + g * 4 + 2];
            ulonglong2 D  = xs2[p * 32 + g * 4 + 3];
            unsigned long long accA = fma2(A.x, wa0.x, 0ull);
            unsigned long long accB = fma2(A.x, wb0.x, 0ull);
            accA = fma2(A.y,  wa0.y, accA);  accB = fma2(A.y,  wb0.y, accB);
            accA = fma2(Bq.x, wa1.x, accA);  accB = fma2(Bq.x, wb1.x, accB);
            accA = fma2(Bq.y, wa1.y, accA);  accB = fma2(Bq.y, wb1.y, accB);
            accA = fma2(C.x,  wa2.x, accA);  accB = fma2(C.x,  wb2.x, accB);
            accA = fma2(C.y,  wa2.y, accA);  accB = fma2(C.y,  wb2.y, accB);
            accA = fma2(D.x,  wa3.x, accA);  accB = fma2(D.x,  wb3.x, accB);
            accA = fma2(D.y,  wa3.y, accA);  accB = fma2(D.y,  wb3.y, accB);
            float loA, hiA, loB, hiB;
            asm("mov.b64 {%0, %1}, %2;" : "=f"(loA), "=f"(hiA) : "l"(accA));
            asm("mov.b64 {%0, %1}, %2;" : "=f"(loB), "=f"(hiB) : "l"(accB));
            float sA = loA + hiA;
            float sB = loB + hiB;
            int n = g * 9 + p;
            su[n * USTRIDE + tid] = sA;
            su[n * USTRIDE + tid + 128] = sB;
            vmeanA += sA;
            vmeanB += sB;
        }
    }
    __syncthreads();

    // ---- routing: two sequential passes (colA = grp, colB = grp+8) ----
#pragma unroll 1
    for (int pass = 0; pass < 2; pass++) {
        const int col = tid + pass * 128;
        const int go = grp + pass * 8;       // o group for this pass
        const float vmean = pass ? vmeanB : vmeanA;

        // read transposed rows: rows[j*16+k] = u[16j+lane][go*16+k]
        float rows[80];
#pragma unroll
        for (int j = 0; j < 5; j++) {
            int n = 16 * j + lane;
            if (n >= 72) n -= 72;            // wrap; masked later (e4=0)
            const float4* rp = reinterpret_cast<const float4*>(su + n * USTRIDE + go * 16);
            float4 r0 = rp[0], r1 = rp[1], r2 = rp[2], r3 = rp[3];
            rows[j * 16 + 0] = r0.x;  rows[j * 16 + 1] = r0.y;
            rows[j * 16 + 2] = r0.z;  rows[j * 16 + 3] = r0.w;
            rows[j * 16 + 4] = r1.x;  rows[j * 16 + 5] = r1.y;
            rows[j * 16 + 6] = r1.z;  rows[j * 16 + 7] = r1.w;
            rows[j * 16 + 8] = r2.x;  rows[j * 16 + 9] = r2.y;
            rows[j * 16 + 10] = r2.z; rows[j * 16 + 11] = r2.w;
            rows[j * 16 + 12] = r3.x; rows[j * 16 + 13] = r3.y;
            rows[j * 16 + 14] = r3.z; rows[j * 16 + 15] = r3.w;
        }

        // initial v, replicated across the 16-lane group
        float v_own = vmean * (1.f / 72.f);
        float vv[16];
#pragma unroll
        for (int k = 0; k < 16; k++) vv[k] = __shfl_sync(FULL, v_own, k, 16);

        float ov = 0.f;
#pragma unroll
        for (int it = 0; it < 3; it++) {
            float sq = 0.f;
#pragma unroll
            for (int k = 0; k < 16; k++) sq = fmaf(vv[k], vv[k], sq);
            float rn = rsqrtf(fmaxf(sq, 1e-24f));

            float e[5];
#pragma unroll
            for (int j = 0; j < 5; j++) {
                float d = 0.f;
#pragma unroll
                for (int k = 0; k < 16; k++) d = fmaf(rows[j * 16 + k], vv[k], d);
                e[j] = __expf(d * rn);
            }
            if (lane >= 8) e[4] = 0.f;

            float ssum = ((e[0] + e[1]) + (e[2] + e[3])) + e[4];
            ssum += __shfl_xor_sync(FULL, ssum, 8);
            ssum += __shfl_xor_sync(FULL, ssum, 4);
            ssum += __shfl_xor_sync(FULL, ssum, 2);
            ssum += __shfl_xor_sync(FULL, ssum, 1);

            float a[16];
#pragma unroll
            for (int k = 0; k < 16; k++) {
                float acc = e[0] * rows[k];
                acc = fmaf(e[1], rows[16 + k], acc);
                acc = fmaf(e[2], rows[32 + k], acc);
                acc = fmaf(e[3], rows[48 + k], acc);
                acc = fmaf(e[4], rows[64 + k], acc);
                a[k] = acc;
            }

            // reduce-scatter: lane s ends with total a[s]
#pragma unroll
            for (int mm = 0; mm < 4; mm++) {
                const int m = 8 >> mm;
                bool up = (lane & m) != 0;
#pragma unroll
                for (int i = 0; i < 16; i++) {
                    if (i >= m) continue;
                    float send = up ? a[i] : a[i + m];
                    float got = __shfl_xor_sync(FULL, send, m);
                    a[i] = (up ? a[i + m] : a[i]) + got;
                }
            }
            float vfin = __fdividef(a[0], ssum);

            if (it < 2) {
#pragma unroll
                for (int k = 0; k < 16; k++) vv[k] = __shfl_sync(FULL, vfin, k, 16);
            } else {
                float s2 = vfin * vfin;
                s2 += __shfl_xor_sync(FULL, s2, 8);
                s2 += __shfl_xor_sync(FULL, s2, 4);
                s2 += __shfl_xor_sync(FULL, s2, 2);
                s2 += __shfl_xor_sync(FULL, s2, 1);
                float norm = sqrtf(s2);
                ov = vfin * __fdividef(norm, 1.f + s2);
            }
        }

        out[((b * 256 + col) * 32 + h) * 32 + w] = ov;
    }
}

extern "C" void kernel_launch(void* const* d_in, const int* in_sizes, int n_in,
                              void* d_out, int out_size) {
    const float* x = (const float*)d_in[0];    // [2,128,32,32]
    const float* w = (const float*)d_in[1];    // [16,16,16,3,3]
    float* out = (float*)d_out;                // [2,256,32,32]

    const int smem_bytes = (1152 + 72 * USTRIDE) * 4;   // 79488 B
    cudaFuncSetAttribute(capsule_kernel,
                         cudaFuncAttributeMaxDynamicSharedMemorySize, smem_bytes);

    wt_transpose<<<36, 256>>>(w);
    capsule_kernel<<<2048, 128, smem_bytes>>>(x, out);
}

// round 8
// speedup vs baseline: 3.1848x; 1.0563x over previous
#include <cuda_runtime.h>
#include <cuda_fp16.h>
#include <float.h>
#include <math.h>

// CapsuleConv2d: B=2, Cin=128, H=W=32, weight [O=16,L=16,M=16,3,3]
// 1 CTA per (b,h,w), 128 threads, thread computes TWO columns: ol = tid, tid+128.
//  - priors (fp32 f32x2 FMA) streamed to smem u[n][ol] in fp16 (38KB -> 3+ CTAs/SM)
//  - routing reads transposed rows back as half2 (packed, 40 regs), unpacks at use
//  - per-iter cross-lane: 4 + 15 + 16 shfl within 16-lane groups

__device__ float4 g_wT4[9 * 4 * 256];  // [(p*4+q)*256 + ol] = W[ol][4q..4q+3][p]

__global__ void wt_transpose(const float* __restrict__ w) {
    int idx = blockIdx.x * 256 + threadIdx.x;   // 9216 total
    int p  = idx >> 10;
    int q  = (idx >> 8) & 3;
    int ol = idx & 255;
    g_wT4[idx] = make_float4(w[(ol * 16 + 4 * q + 0) * 9 + p],
                             w[(ol * 16 + 4 * q + 1) * 9 + p],
                             w[(ol * 16 + 4 * q + 2) * 9 + p],
                             w[(ol * 16 + 4 * q + 3) * 9 + p]);
}

__device__ __forceinline__ unsigned long long fma2(unsigned long long a,
                                                   unsigned long long b,
                                                   unsigned long long c) {
    unsigned long long d;
    asm("fma.rn.f32x2 %0, %1, %2, %3;" : "=l"(d) : "l"(a), "l"(b), "l"(c));
    return d;
}

#define USTRIDE_H 264   // row stride in halfs (528 B): conflict-free phase pattern

__global__ __launch_bounds__(128, 3)
void capsule_kernel(const float* __restrict__ x, float* __restrict__ out) {
    extern __shared__ __align__(16) float smem[];
    float* xs = smem;                                   // 9*128 patch (fp32)
    __half* su = reinterpret_cast<__half*>(smem + 1152); // 72 * USTRIDE_H halfs

    const unsigned FULL = 0xffffffffu;
    const int tid = threadIdx.x;     // colA = tid, colB = tid + 128
    const int lane = tid & 15;       // l
    const int grp = tid >> 4;        // o for colA (0..7); colB is grp+8
    const int bid = blockIdx.x;
    const int b = bid >> 10;
    const int h = (bid >> 5) & 31;
    const int w = bid & 31;

    // Stage 3x3 patch (zero-padded): 9 pixels x 128 channels
    for (int idx = tid; idx < 9 * 128; idx += 128) {
        int p = idx >> 7;
        int c = idx & 127;
        int hh = h + p / 3 - 1;
        int ww = w + p % 3 - 1;
        float v = 0.f;
        if ((unsigned)hh < 32u && (unsigned)ww < 32u)
            v = x[((b * 128 + c) * 32 + hh) * 32 + ww];
        xs[idx] = v;
    }
    __syncthreads();

    // ---- priors for BOTH columns; each xs load feeds 2 FMA chains ----
    float vmeanA = 0.f, vmeanB = 0.f;
    const ulonglong2* xs2 = reinterpret_cast<const ulonglong2*>(xs);
    const ulonglong2* wp = reinterpret_cast<const ulonglong2*>(g_wT4);
#pragma unroll
    for (int p = 0; p < 9; p++) {
        ulonglong2 wa0 = wp[(p * 4 + 0) * 256 + tid];
        ulonglong2 wa1 = wp[(p * 4 + 1) * 256 + tid];
        ulonglong2 wa2 = wp[(p * 4 + 2) * 256 + tid];
        ulonglong2 wa3 = wp[(p * 4 + 3) * 256 + tid];
        ulonglong2 wb0 = wp[(p * 4 + 0) * 256 + tid + 128];
        ulonglong2 wb1 = wp[(p * 4 + 1) * 256 + tid + 128];
        ulonglong2 wb2 = wp[(p * 4 + 2) * 256 + tid + 128];
        ulonglong2 wb3 = wp[(p * 4 + 3) * 256 + tid + 128];
#pragma unroll
        for (int g = 0; g < 8; g++) {
            ulonglong2 A  = xs2[p * 32 + g * 4 + 0];
            ulonglong2 Bq = xs2[p * 32 + g * 4 + 1];
            ulonglong2 C  = xs2[p * 32 + g * 4 + 2];
            ulonglong2 D  = xs2[p * 32 + g * 4 + 3];
            unsigned long long accA = fma2(A.x, wa0.x, 0ull);
            unsigned long long accB = fma2(A.x, wb0.x, 0ull);
            accA = fma2(A.y,  wa0.y, accA);  accB = fma2(A.y,  wb0.y, accB);
            accA = fma2(Bq.x, wa1.x, accA);  accB = fma2(Bq.x, wb1.x, accB);
            accA = fma2(Bq.y, wa1.y, accA);  accB = fma2(Bq.y, wb1.y, accB);
            accA = fma2(C.x,  wa2.x, accA);  accB = fma2(C.x,  wb2.x, accB);
            accA = fma2(C.y,  wa2.y, accA);  accB = fma2(C.y,  wb2.y, accB);
            accA = fma2(D.x,  wa3.x, accA);  accB = fma2(D.x,  wb3.x, accB);
            accA = fma2(D.y,  wa3.y, accA);  accB = fma2(D.y,  wb3.y, accB);
            float loA, hiA, loB, hiB;
            asm("mov.b64 {%0, %1}, %2;" : "=f"(loA), "=f"(hiA) : "l"(accA));
            asm("mov.b64 {%0, %1}, %2;" : "=f"(loB), "=f"(hiB) : "l"(accB));
            float sA = loA + hiA;
            float sB = loB + hiB;
            int n = g * 9 + p;
            su[n * USTRIDE_H + tid]       = __float2half_rn(sA);
            su[n * USTRIDE_H + tid + 128] = __float2half_rn(sB);
            vmeanA += sA;
            vmeanB += sB;
        }
    }
    __syncthreads();

    // ---- routing: two sequential passes (colA = grp, colB = grp+8) ----
#pragma unroll 1
    for (int pass = 0; pass < 2; pass++) {
        const int col = tid + pass * 128;
        const int go = grp + pass * 8;
        const float vmean = pass ? vmeanB : vmeanA;

        // read transposed rows packed: rows2[j*8+i] = half2(u[16j+lane][go*16+2i], ..+2i+1)
        __half2 rows2[40];
#pragma unroll
        for (int j = 0; j < 5; j++) {
            int n = 16 * j + lane;
            if (n >= 72) n -= 72;            // wrap; masked later (e4=0)
            const uint4* rp = reinterpret_cast<const uint4*>(su + n * USTRIDE_H + go * 16);
            uint4 q0 = rp[0];                // halfs 0..7
            uint4 q1 = rp[1];                // halfs 8..15
            rows2[j * 8 + 0] = *reinterpret_cast<__half2*>(&q0.x);
            rows2[j * 8 + 1] = *reinterpret_cast<__half2*>(&q0.y);
            rows2[j * 8 + 2] = *reinterpret_cast<__half2*>(&q0.z);
            rows2[j * 8 + 3] = *reinterpret_cast<__half2*>(&q0.w);
            rows2[j * 8 + 4] = *reinterpret_cast<__half2*>(&q1.x);
            rows2[j * 8 + 5] = *reinterpret_cast<__half2*>(&q1.y);
            rows2[j * 8 + 6] = *reinterpret_cast<__half2*>(&q1.z);
            rows2[j * 8 + 7] = *reinterpret_cast<__half2*>(&q1.w);
        }

        // initial v, replicated across the 16-lane group
        float v_own = vmean * (1.f / 72.f);
        float vv[16];
#pragma unroll
        for (int k = 0; k < 16; k++) vv[k] = __shfl_sync(FULL, v_own, k, 16);

        float ov = 0.f;
#pragma unroll
        for (int it = 0; it < 3; it++) {
            float sq = 0.f;
#pragma unroll
            for (int k = 0; k < 16; k++) sq = fmaf(vv[k], vv[k], sq);
            float rn = rsqrtf(fmaxf(sq, 1e-24f));

            // logits -> exp
            float e[5];
#pragma unroll
            for (int j = 0; j < 5; j++) {
                float d = 0.f;
#pragma unroll
                for (int i = 0; i < 8; i++) {
                    float2 f = __half22float2(rows2[j * 8 + i]);
                    d = fmaf(f.x, vv[2 * i], d);
                    d = fmaf(f.y, vv[2 * i + 1], d);
                }
                e[j] = __expf(d * rn);
            }
            if (lane >= 8) e[4] = 0.f;

            float ssum = ((e[0] + e[1]) + (e[2] + e[3])) + e[4];
            ssum += __shfl_xor_sync(FULL, ssum, 8);
            ssum += __shfl_xor_sync(FULL, ssum, 4);
            ssum += __shfl_xor_sync(FULL, ssum, 2);
            ssum += __shfl_xor_sync(FULL, ssum, 1);

            // weighted accumulation
            float a[16];
#pragma unroll
            for (int i = 0; i < 8; i++) {
                float ax = 0.f, ay = 0.f;
#pragma unroll
                for (int j = 0; j < 5; j++) {
                    float2 f = __half22float2(rows2[j * 8 + i]);
                    ax = fmaf(e[j], f.x, ax);
                    ay = fmaf(e[j], f.y, ay);
                }
                a[2 * i] = ax;
                a[2 * i + 1] = ay;
            }

            // reduce-scatter: lane s ends with total a[s]
#pragma unroll
            for (int mm = 0; mm < 4; mm++) {
                const int m = 8 >> mm;
                bool up = (lane & m) != 0;
#pragma unroll
                for (int i = 0; i < 16; i++) {
                    if (i >= m) continue;
                    float send = up ? a[i] : a[i + m];
                    float got = __shfl_xor_sync(FULL, send, m);
                    a[i] = (up ? a[i + m] : a[i]) + got;
                }
            }
            float vfin = __fdividef(a[0], ssum);

            if (it < 2) {
#pragma unroll
                for (int k = 0; k < 16; k++) vv[k] = __shfl_sync(FULL, vfin, k, 16);
            } else {
                float s2 = vfin * vfin;
                s2 += __shfl_xor_sync(FULL, s2, 8);
                s2 += __shfl_xor_sync(FULL, s2, 4);
                s2 += __shfl_xor_sync(FULL, s2, 2);
                s2 += __shfl_xor_sync(FULL, s2, 1);
                float norm = sqrtf(s2);
                ov = vfin * __fdividef(norm, 1.f + s2);
            }
        }

        out[((b * 256 + col) * 32 + h) * 32 + w] = ov;
    }
}

extern "C" void kernel_launch(void* const* d_in, const int* in_sizes, int n_in,
                              void* d_out, int out_size) {
    const float* x = (const float*)d_in[0];    // [2,128,32,32]
    const float* w = (const float*)d_in[1];    // [16,16,16,3,3]
    float* out = (float*)d_out;                // [2,256,32,32]

    const int smem_bytes = 1152 * 4 + 72 * USTRIDE_H * 2;   // 4608 + 38016 = 42624 B
    cudaFuncSetAttribute(capsule_kernel,
                         cudaFuncAttributeMaxDynamicSharedMemorySize, smem_bytes);

    wt_transpose<<<36, 256>>>(w);
    capsule_kernel<<<2048, 128, smem_bytes>>>(x, out);
}